// round 2
// baseline (speedup 1.0000x reference)
#include <cuda_runtime.h>

// AffineCouplingLayer: B=524288 rows, D=64, H=64, M=32, U=32
//   cin = x[:,0::2]                       (32)
//   h1  = relu(cin @ W1 + b1)             (64)
//   h2  = relu(h1  @ W2 + b2)             (64)
//   st  = h2 @ W3 + b3                    (64)  -> s = tanh(st[:32]), t = st[32:]
//   y   = x with odd cols = x_odd*exp(s)+t
// Output layout: y (B*64 floats) followed by s (B*32 floats).

#define D_DIM 64
#define H_DIM 64
#define M_DIM 32
#define TPB   256

typedef unsigned long long u64;

__device__ __forceinline__ u64 pack2(float v) {
    u64 r;
    asm("mov.b64 %0, {%1, %1};" : "=l"(r) : "f"(v));
    return r;
}
__device__ __forceinline__ void unpack2(u64 v, float& a, float& b) {
    asm("mov.b64 {%0, %1}, %2;" : "=f"(a), "=f"(b) : "l"(v));
}
__device__ __forceinline__ void fma2(u64& d, u64 a, u64 b) {
    // packed fp32x2 FMA: d = a*b + d (elementwise) — 2x fp32 throughput vs FFMA
    asm("fma.rn.f32x2 %0, %1, %2, %0;" : "+l"(d) : "l"(a), "l"(b));
}

// One dense layer: hout[j] = act( sum_k hin[k]*W[k*64+j] + b[j] ), j in [0,64)
// Accumulators held as 32 packed f32x2 pairs; weights read as LDS.128
// (2 packed pairs per load) -> per 4 FMAs: 1 LDS.128 + 2 FFMA2.
template <int K, bool RELU>
__device__ __forceinline__ void dense64(const float* hin,
                                        const float* __restrict__ sW,
                                        const float* __restrict__ sb,
                                        float* hout) {
    u64 acc[32];
    const ulonglong2* bb = (const ulonglong2*)sb;
#pragma unroll
    for (int p = 0; p < 16; p++) {
        ulonglong2 b2 = bb[p];
        acc[2 * p]     = b2.x;
        acc[2 * p + 1] = b2.y;
    }
#pragma unroll
    for (int k = 0; k < K; k++) {
        u64 a2 = pack2(hin[k]);
        const ulonglong2* wr = (const ulonglong2*)(sW + k * H_DIM);
#pragma unroll
        for (int p = 0; p < 16; p++) {
            ulonglong2 w = wr[p];
            fma2(acc[2 * p],     a2, w.x);
            fma2(acc[2 * p + 1], a2, w.y);
        }
    }
#pragma unroll
    for (int p = 0; p < 32; p++) {
        float a, b;
        unpack2(acc[p], a, b);
        if (RELU) { a = fmaxf(a, 0.0f); b = fmaxf(b, 0.0f); }
        hout[2 * p]     = a;
        hout[2 * p + 1] = b;
    }
}

__global__ void __launch_bounds__(TPB)
affine_coupling_kernel(const float* __restrict__ x,
                       const float* __restrict__ W1, const float* __restrict__ b1,
                       const float* __restrict__ W2, const float* __restrict__ b2,
                       const float* __restrict__ W3, const float* __restrict__ b3,
                       float* __restrict__ out, int nrows) {
    __shared__ __align__(16) float sW1[M_DIM * H_DIM];
    __shared__ __align__(16) float sW2[H_DIM * H_DIM];
    __shared__ __align__(16) float sW3[H_DIM * H_DIM];
    __shared__ __align__(16) float sb1[H_DIM];
    __shared__ __align__(16) float sb2[H_DIM];
    __shared__ __align__(16) float sb3[H_DIM];

    const int tid = threadIdx.x;
#pragma unroll 4
    for (int i = tid; i < M_DIM * H_DIM; i += TPB) sW1[i] = __ldg(W1 + i);
#pragma unroll 4
    for (int i = tid; i < H_DIM * H_DIM; i += TPB) sW2[i] = __ldg(W2 + i);
#pragma unroll 4
    for (int i = tid; i < H_DIM * H_DIM; i += TPB) sW3[i] = __ldg(W3 + i);
    if (tid < H_DIM) {
        sb1[tid] = __ldg(b1 + tid);
        sb2[tid] = __ldg(b2 + tid);
        sb3[tid] = __ldg(b3 + tid);
    }
    __syncthreads();

    const int row = blockIdx.x * TPB + tid;
    if (row >= nrows) return;

    const float4* xr = (const float4*)(x + (size_t)row * D_DIM);

    // Gather even columns: float4 i covers cols 4i..4i+3; .x = col 4i, .z = col 4i+2
    float cin[M_DIM];
#pragma unroll
    for (int i = 0; i < 16; i++) {
        float4 v = xr[i];
        cin[2 * i]     = v.x;
        cin[2 * i + 1] = v.z;
    }

    float h1[H_DIM];
    dense64<M_DIM, true>(cin, sW1, sb1, h1);
    float h2[H_DIM];
    dense64<H_DIM, true>(h1, sW2, sb2, h2);
    float st[H_DIM];
    dense64<H_DIM, false>(h2, sW3, sb3, st);

    // s = tanh(st[:32]) via 1 - 2/(exp(2x)+1); es = exp(s); t = st[32:]
    float sv[32], es[32], tt[32];
#pragma unroll
    for (int j = 0; j < 32; j++) {
        float e2 = __expf(2.0f * st[j]);
        float s  = 1.0f - __fdividef(2.0f, e2 + 1.0f);
        sv[j] = s;
        es[j] = __expf(s);
        tt[j] = st[32 + j];
    }

    // y: reload the row (L1-hot), modify odd columns, store as float4.
    // odd col 4i+1 -> s-index 2i ; odd col 4i+3 -> s-index 2i+1
    float4* oy = (float4*)(out + (size_t)row * D_DIM);
#pragma unroll
    for (int i = 0; i < 16; i++) {
        float4 v = xr[i];
        v.y = fmaf(v.y, es[2 * i],     tt[2 * i]);
        v.w = fmaf(v.w, es[2 * i + 1], tt[2 * i + 1]);
        oy[i] = v;
    }

    // s output follows the full y block
    float4* os = (float4*)(out + (size_t)nrows * D_DIM + (size_t)row * 32);
#pragma unroll
    for (int i = 0; i < 8; i++) {
        os[i] = make_float4(sv[4 * i], sv[4 * i + 1], sv[4 * i + 2], sv[4 * i + 3]);
    }
}

extern "C" void kernel_launch(void* const* d_in, const int* in_sizes, int n_in,
                              void* d_out, int out_size) {
    const float* x  = (const float*)d_in[0];
    const float* W1 = (const float*)d_in[1];
    const float* b1 = (const float*)d_in[2];
    const float* W2 = (const float*)d_in[3];
    const float* b2 = (const float*)d_in[4];
    const float* W3 = (const float*)d_in[5];
    const float* b3 = (const float*)d_in[6];
    float* out = (float*)d_out;

    const int nrows = in_sizes[0] / D_DIM;  // 524288
    const int grid  = (nrows + TPB - 1) / TPB;

    affine_coupling_kernel<<<grid, TPB>>>(x, W1, b1, W2, b2, W3, b3, out, nrows);
}

// round 4
// speedup vs baseline: 2.7409x; 2.7409x over previous
#include <cuda_runtime.h>
#include <cuda_bf16.h>
#include <cstdint>

// AffineCouplingLayer via legacy tensor pipe (mma.sync bf16, sm_100-safe).
// B=524288 rows, D=64. cin = even cols (32).
//   h1 = relu(cin@W1+b1); h2 = relu(h1@W2+b2); st = h2@W3+b3
//   s = tanh(st[:32]); y = x with odd cols = x_odd*exp(s)+t
// out = [ y (B*64 f32) | s (B*32 f32) ]
//
// Per-warp tile M=32 (2 x m16 tiles), N=64 (8 x n8 tiles). Activations stay in
// registers: C fragment of layer L == A fragment of layer L+1 (pure repack).
// Weights: bf16 hi/lo split in swizzled SMEM, fetched with ldmatrix.x2.trans.
// 3 mma products per logical GEMM: Ah@Bh + Ah@Bl + Al@Bh (err ~2^-17).

#define TPB          128
#define ROWS_PER_CTA 128

// ---- SMEM layout (bytes) ----
// weight rows: L1 k=0..31 (rb 0), L2 k rows 32..95 (rb 32), L3 rows 96..159 (rb 96)
#define WHI     0            // 160 rows * 128B = 20480
#define WLO     20480
#define BIAS_O  40960        // 192 f32 = 768B
#define SS_OFF  41728        // 128 * 33 f32 = 16896B
#define TS_OFF  58624        // 128 * 33 f32
#define SMEM_BYTES 75520

#define SWZ(o) ((o) ^ (((o) >> 3) & 0x70))

static __device__ __forceinline__ uint32_t smem_u32_of(const void* p) {
    uint32_t a;
    asm("{ .reg .u64 t; cvta.to.shared.u64 t, %1; cvt.u32.u64 %0, t; }" : "=r"(a) : "l"(p));
    return a;
}

// pack two f32 -> bf16x2 (lo in low half)
static __device__ __forceinline__ uint32_t pack_bf16(float lo, float hi) {
    uint32_t r;
    asm("cvt.rn.bf16x2.f32 %0, %1, %2;" : "=r"(r) : "f"(hi), "f"(lo));
    return r;
}

// hi/lo split of a f32 pair into two bf16x2 regs
static __device__ __forceinline__ void split2(float u, float v, uint32_t& h, uint32_t& l) {
    h = pack_bf16(u, v);
    float hu = __uint_as_float(h << 16);
    float hv = __uint_as_float(h & 0xFFFF0000u);
    l = pack_bf16(u - hu, v - hv);
}

static __device__ __forceinline__ void mma16816(float* c, const uint32_t* a,
                                                uint32_t b0, uint32_t b1) {
    asm volatile(
        "mma.sync.aligned.m16n8k16.row.col.f32.bf16.bf16.f32 "
        "{%0,%1,%2,%3}, {%4,%5,%6,%7}, {%8,%9}, {%0,%1,%2,%3};"
        : "+f"(c[0]), "+f"(c[1]), "+f"(c[2]), "+f"(c[3])
        : "r"(a[0]), "r"(a[1]), "r"(a[2]), "r"(a[3]), "r"(b0), "r"(b1));
}

static __device__ __forceinline__ void ldsm2t(uint32_t addr, uint32_t& b0, uint32_t& b1) {
    asm volatile("ldmatrix.sync.aligned.m8n8.x2.trans.shared.b16 {%0,%1}, [%2];"
                 : "=r"(b0), "=r"(b1) : "r"(addr));
}

// One GEMM layer: C[2][8][4] = (Ah+Al) @ (Bh+Bl), dropping Al@Bl.
template <int KS>
static __device__ __forceinline__ void run_layer(uint32_t smb, int row_rb, int lane,
                                                 const uint32_t Ah[2][4][4],
                                                 const uint32_t Al[2][4][4],
                                                 float C[2][8][4]) {
#pragma unroll
    for (int mt = 0; mt < 2; mt++)
#pragma unroll
        for (int j = 0; j < 8; j++)
#pragma unroll
            for (int q = 0; q < 4; q++) C[mt][j][q] = 0.0f;

#pragma unroll
    for (int s = 0; s < KS; s++) {
        int rowc = row_rb + s * 16 + (lane & 15);   // ldsm row for this lane
        uint32_t base = (uint32_t)rowc * 128;
        uint32_t x7 = (uint32_t)(rowc & 7);
#pragma unroll
        for (int j = 0; j < 8; j++) {
            uint32_t coff = base + (((uint32_t)j ^ x7) << 4);   // swizzled 16B chunk
            uint32_t bh0, bh1, bl0, bl1;
            ldsm2t(smb + WHI + coff, bh0, bh1);
            ldsm2t(smb + WLO + coff, bl0, bl1);
#pragma unroll
            for (int mt = 0; mt < 2; mt++) {
                mma16816(C[mt][j], Ah[mt][s], bh0, bh1);
                mma16816(C[mt][j], Al[mt][s], bh0, bh1);
                mma16816(C[mt][j], Ah[mt][s], bl0, bl1);
            }
        }
    }
}

// bias + relu + hi/lo split: C (this layer) -> A fragments (next layer)
static __device__ __forceinline__ void epi_relu_split(const float* bias, int tid4,
                                                      const float C[2][8][4],
                                                      uint32_t Ah[2][4][4],
                                                      uint32_t Al[2][4][4]) {
#pragma unroll
    for (int j = 0; j < 8; j++) {
        float b0 = bias[8 * j + 2 * tid4];
        float b1 = bias[8 * j + 2 * tid4 + 1];
#pragma unroll
        for (int mt = 0; mt < 2; mt++) {
            float v0 = fmaxf(C[mt][j][0] + b0, 0.0f);
            float v1 = fmaxf(C[mt][j][1] + b1, 0.0f);
            float v2 = fmaxf(C[mt][j][2] + b0, 0.0f);
            float v3 = fmaxf(C[mt][j][3] + b1, 0.0f);
            int s = j >> 1;
            int fi = (j & 1) * 2;          // even j -> a0/a1, odd j -> a2/a3
            split2(v0, v1, Ah[mt][s][fi],     Al[mt][s][fi]);
            split2(v2, v3, Ah[mt][s][fi + 1], Al[mt][s][fi + 1]);
        }
    }
}

__global__ void __launch_bounds__(TPB, 3)
affine_coupling_hmma(const float* __restrict__ x,
                     const float* __restrict__ W1, const float* __restrict__ b1,
                     const float* __restrict__ W2, const float* __restrict__ b2,
                     const float* __restrict__ W3, const float* __restrict__ b3,
                     float* __restrict__ out, int nrows) {
    extern __shared__ char sm[];
    const uint32_t smb = smem_u32_of(sm);

    const int tid  = threadIdx.x;
    const int wid  = tid >> 5;
    const int lane = tid & 31;
    const int g    = lane >> 2;     // group row (0..7)
    const int t4   = lane & 3;      // col pair index

    // ---- weight prep: bf16 hi/lo, SW128 swizzled [k][n] rows of 128B ----
    for (int e = tid; e < 10240; e += TPB) {
        const float* src; int rel, rb;
        if (e < 2048)      { src = W1; rel = e;        rb = 0;  }
        else if (e < 6144) { src = W2; rel = e - 2048; rb = 32; }
        else               { src = W3; rel = e - 6144; rb = 96; }
        int k = rel >> 6, n = rel & 63;
        float w = __ldg(src + rel);
        __nv_bfloat16 h = __float2bfloat16(w);
        float hf = __bfloat162float(h);
        __nv_bfloat16 l = __float2bfloat16(w - hf);
        uint32_t off = SWZ((uint32_t)((rb + k) * 128 + n * 2));
        *(__nv_bfloat16*)(sm + WHI + off) = h;
        *(__nv_bfloat16*)(sm + WLO + off) = l;
    }
    float* bias = (float*)(sm + BIAS_O);
    if (tid < 64) {
        bias[tid]       = __ldg(b1 + tid);
        bias[64 + tid]  = __ldg(b2 + tid);
        bias[128 + tid] = __ldg(b3 + tid);
    }
    __syncthreads();

    float* ss = (float*)(sm + SS_OFF);
    float* ts = (float*)(sm + TS_OFF);

    const int ntiles = nrows / ROWS_PER_CTA;

    for (int tile = blockIdx.x; tile < ntiles; tile += gridDim.x) {
        const float* xb = x + (size_t)tile * ROWS_PER_CTA * 64;

        uint32_t Ah[2][4][4], Al[2][4][4];
        float C[2][8][4];

        // ---- layer-1 A fragments straight from global (cin = even cols) ----
#pragma unroll
        for (int mt = 0; mt < 2; mt++) {
            int r0 = wid * 32 + mt * 16 + g;
            int r1 = r0 + 8;
#pragma unroll
            for (int s = 0; s < 2; s++) {
                const float4* p0 = (const float4*)(xb + r0 * 64 + s * 32) + t4;
                const float4* p1 = (const float4*)(xb + r1 * 64 + s * 32) + t4;
                float4 f0 = __ldg(p0);       // x cols 32s+4t .. +3 (row g)
                float4 f1 = __ldg(p0 + 4);   // x cols 32s+16+4t    (row g)
                float4 f2 = __ldg(p1);
                float4 f3 = __ldg(p1 + 4);
                split2(f0.x, f0.z, Ah[mt][s][0], Al[mt][s][0]);  // a0: row g,  k lo
                split2(f2.x, f2.z, Ah[mt][s][1], Al[mt][s][1]);  // a1: row g+8
                split2(f1.x, f1.z, Ah[mt][s][2], Al[mt][s][2]);  // a2: row g,  k hi
                split2(f3.x, f3.z, Ah[mt][s][3], Al[mt][s][3]);  // a3
            }
        }

        // ---- 3 GEMM layers ----
        run_layer<2>(smb, 0, lane, Ah, Al, C);
        epi_relu_split(bias, t4, C, Ah, Al);
        run_layer<4>(smb, 32, lane, Ah, Al, C);
        epi_relu_split(bias + 64, t4, C, Ah, Al);
        run_layer<4>(smb, 96, lane, Ah, Al, C);

        // ---- layer-3 epilogue: s=tanh(st[:32]) -> ss, t=st[32:] -> ts ----
#pragma unroll
        for (int mt = 0; mt < 2; mt++) {
            int r0 = wid * 32 + mt * 16 + g;
#pragma unroll
            for (int j = 0; j < 8; j++) {
                int cs = 8 * (j & 3) + 2 * t4;      // staged column
                float b0 = bias[128 + 8 * j + 2 * t4];
                float b1 = bias[128 + 8 * j + 2 * t4 + 1];
                float v0 = C[mt][j][0] + b0;
                float v1 = C[mt][j][1] + b1;
                float v2 = C[mt][j][2] + b0;
                float v3 = C[mt][j][3] + b1;
                if (j < 4) {  // s half: tanh
                    v0 = 1.0f - __fdividef(2.0f, __expf(2.0f * v0) + 1.0f);
                    v1 = 1.0f - __fdividef(2.0f, __expf(2.0f * v1) + 1.0f);
                    v2 = 1.0f - __fdividef(2.0f, __expf(2.0f * v2) + 1.0f);
                    v3 = 1.0f - __fdividef(2.0f, __expf(2.0f * v3) + 1.0f);
                    ss[r0 * 33 + cs]           = v0;
                    ss[r0 * 33 + cs + 1]       = v1;
                    ss[(r0 + 8) * 33 + cs]     = v2;
                    ss[(r0 + 8) * 33 + cs + 1] = v3;
                } else {
                    ts[r0 * 33 + cs]           = v0;
                    ts[r0 * 33 + cs + 1]       = v1;
                    ts[(r0 + 8) * 33 + cs]     = v2;
                    ts[(r0 + 8) * 33 + cs + 1] = v3;
                }
            }
        }
        __syncthreads();

        // ---- coalesced output pass ----
        {
            const float4* xt = (const float4*)xb;
            float4* oy = (float4*)out + (size_t)tile * (ROWS_PER_CTA * 16);
#pragma unroll
            for (int it = 0; it < 16; it++) {
                int f = it * TPB + tid;
                int row = f >> 4, q = f & 15;
                float4 v = __ldg(xt + f);
                float s0 = ss[row * 33 + 2 * q];
                float s1 = ss[row * 33 + 2 * q + 1];
                float t0 = ts[row * 33 + 2 * q];
                float t1 = ts[row * 33 + 2 * q + 1];
                v.y = fmaf(v.y, __expf(s0), t0);
                v.w = fmaf(v.w, __expf(s1), t1);
                oy[f] = v;
            }
            float4* os = (float4*)(out + (size_t)nrows * 64) + (size_t)tile * (ROWS_PER_CTA * 8);
#pragma unroll
            for (int it = 0; it < 8; it++) {
                int f = it * TPB + tid;
                int row = f >> 3, c4 = (f & 7) * 4;
                os[f] = make_float4(ss[row * 33 + c4],     ss[row * 33 + c4 + 1],
                                    ss[row * 33 + c4 + 2], ss[row * 33 + c4 + 3]);
            }
        }
        __syncthreads();   // staging reused next tile
    }
}

extern "C" void kernel_launch(void* const* d_in, const int* in_sizes, int n_in,
                              void* d_out, int out_size) {
    const float* x  = (const float*)d_in[0];
    const float* W1 = (const float*)d_in[1];
    const float* b1 = (const float*)d_in[2];
    const float* W2 = (const float*)d_in[3];
    const float* b2 = (const float*)d_in[4];
    const float* W3 = (const float*)d_in[5];
    const float* b3 = (const float*)d_in[6];
    float* out = (float*)d_out;

    const int nrows = in_sizes[0] / 64;
    const int ntiles = nrows / ROWS_PER_CTA;
    int grid = 444;                      // 3 CTAs/SM * 148 SMs
    if (grid > ntiles) grid = ntiles;

    static int smem_set = 0;
    if (!smem_set) {
        cudaFuncSetAttribute(affine_coupling_hmma,
                             cudaFuncAttributeMaxDynamicSharedMemorySize, SMEM_BYTES);
        smem_set = 1;
    }
    affine_coupling_hmma<<<grid, TPB, SMEM_BYTES>>>(x, W1, b1, W2, b2, W3, b3, out, nrows);
}

// round 5
// speedup vs baseline: 2.9224x; 1.0662x over previous
#include <cuda_runtime.h>
#include <cuda_bf16.h>
#include <cstdint>

// AffineCouplingLayer via legacy tensor pipe (mma.sync bf16, sm_100-safe).
// B=524288 rows, D=64. cin = even cols (32).
//   h1 = relu(cin@W1+b1); h2 = relu(h1@W2+b2); st = h2@W3+b3
//   s = tanh(st[:32]); y = x with odd cols = x_odd*exp(s)+t
// out = [ y (B*64 f32) | s (B*32 f32) ]
//
// Per-warp tile M=32 (2 x m16), N=64 (8 x n8). Activations stay in registers:
// C fragment of layer L == A fragment of layer L+1 (pure repack).
// Weights: bf16 hi/lo split in swizzled SMEM. ONE ldmatrix.x4.trans fetches
// {bh0,bh1,bl0,bl1} (lanes 0-15 -> WHI rows, lanes 16-31 -> WLO rows).
// 3 mma products per GEMM: Ah@Bh + Al@Bh + Ah@Bl (err ~2^-17), mt-interleaved.

#define TPB          128
#define ROWS_PER_CTA 128

// ---- SMEM layout (bytes) ----
#define WHI     0            // 160 rows * 128B = 20480
#define WLO     20480
#define BIAS_O  40960        // 192 f32
#define SS_OFF  41728        // 128 * 33 f32
#define TS_OFF  58624        // 128 * 33 f32
#define SMEM_BYTES 75520

#define SWZ(o) ((o) ^ (((o) >> 3) & 0x70))

static __device__ __forceinline__ uint32_t smem_u32_of(const void* p) {
    uint32_t a;
    asm("{ .reg .u64 t; cvta.to.shared.u64 t, %1; cvt.u32.u64 %0, t; }" : "=r"(a) : "l"(p));
    return a;
}

static __device__ __forceinline__ uint32_t pack_bf16(float lo, float hi) {
    uint32_t r;
    asm("cvt.rn.bf16x2.f32 %0, %1, %2;" : "=r"(r) : "f"(hi), "f"(lo));
    return r;
}

static __device__ __forceinline__ void split2(float u, float v, uint32_t& h, uint32_t& l) {
    h = pack_bf16(u, v);
    float hu = __uint_as_float(h << 16);
    float hv = __uint_as_float(h & 0xFFFF0000u);
    l = pack_bf16(u - hu, v - hv);
}

static __device__ __forceinline__ void mma16816(float* c, const uint32_t* a,
                                                uint32_t b0, uint32_t b1) {
    asm volatile(
        "mma.sync.aligned.m16n8k16.row.col.f32.bf16.bf16.f32 "
        "{%0,%1,%2,%3}, {%4,%5,%6,%7}, {%8,%9}, {%0,%1,%2,%3};"
        : "+f"(c[0]), "+f"(c[1]), "+f"(c[2]), "+f"(c[3])
        : "r"(a[0]), "r"(a[1]), "r"(a[2]), "r"(a[3]), "r"(b0), "r"(b1));
}

// Fused hi/lo weight fetch: lanes 0-15 address WHI rows, 16-31 WLO rows.
static __device__ __forceinline__ void ldsm4t(uint32_t addr, uint32_t& bh0, uint32_t& bh1,
                                              uint32_t& bl0, uint32_t& bl1) {
    asm volatile("ldmatrix.sync.aligned.m8n8.x4.trans.shared.b16 {%0,%1,%2,%3}, [%4];"
                 : "=r"(bh0), "=r"(bh1), "=r"(bl0), "=r"(bl1) : "r"(addr));
}

// One GEMM layer: C[2][8][4] = (Ah+Al) @ (Bh+Bl), dropping Al@Bl.
// bufb: per-lane smem base (WHI for lanes 0-15, WLO for lanes 16-31).
template <int KS>
static __device__ __forceinline__ void run_layer(uint32_t bufb, int row_rb, int lane15,
                                                 const uint32_t Ah[2][4][4],
                                                 const uint32_t Al[2][4][4],
                                                 float C[2][8][4]) {
#pragma unroll
    for (int mt = 0; mt < 2; mt++)
#pragma unroll
        for (int j = 0; j < 8; j++)
#pragma unroll
            for (int q = 0; q < 4; q++) C[mt][j][q] = 0.0f;

#pragma unroll
    for (int s = 0; s < KS; s++) {
        int rowc = row_rb + s * 16 + lane15;            // k-row this lane addresses
        uint32_t base = bufb + (uint32_t)rowc * 128;
        uint32_t x7 = (uint32_t)(rowc & 7);
#pragma unroll
        for (int j = 0; j < 8; j++) {
            uint32_t addr = base + (((uint32_t)j ^ x7) << 4);
            uint32_t bh0, bh1, bl0, bl1;
            ldsm4t(addr, bh0, bh1, bl0, bl1);
            // interleave the two independent mt accumulator chains
            mma16816(C[0][j], Ah[0][s], bh0, bh1);
            mma16816(C[1][j], Ah[1][s], bh0, bh1);
            mma16816(C[0][j], Al[0][s], bh0, bh1);
            mma16816(C[1][j], Al[1][s], bh0, bh1);
            mma16816(C[0][j], Ah[0][s], bl0, bl1);
            mma16816(C[1][j], Ah[1][s], bl0, bl1);
        }
    }
}

// bias + relu + hi/lo split: C (this layer) -> A fragments (next layer)
static __device__ __forceinline__ void epi_relu_split(const float* bias, int t4,
                                                      const float C[2][8][4],
                                                      uint32_t Ah[2][4][4],
                                                      uint32_t Al[2][4][4]) {
#pragma unroll
    for (int j = 0; j < 8; j++) {
        float b0 = bias[8 * j + 2 * t4];
        float b1 = bias[8 * j + 2 * t4 + 1];
#pragma unroll
        for (int mt = 0; mt < 2; mt++) {
            float v0 = fmaxf(C[mt][j][0] + b0, 0.0f);
            float v1 = fmaxf(C[mt][j][1] + b1, 0.0f);
            float v2 = fmaxf(C[mt][j][2] + b0, 0.0f);
            float v3 = fmaxf(C[mt][j][3] + b1, 0.0f);
            int s = j >> 1;
            int fi = (j & 1) * 2;
            split2(v0, v1, Ah[mt][s][fi],     Al[mt][s][fi]);
            split2(v2, v3, Ah[mt][s][fi + 1], Al[mt][s][fi + 1]);
        }
    }
}

__global__ void __launch_bounds__(TPB, 3)
affine_coupling_hmma(const float* __restrict__ x,
                     const float* __restrict__ W1, const float* __restrict__ b1,
                     const float* __restrict__ W2, const float* __restrict__ b2,
                     const float* __restrict__ W3, const float* __restrict__ b3,
                     float* __restrict__ out, int nrows) {
    extern __shared__ char sm[];
    const uint32_t smb = smem_u32_of(sm);

    const int tid  = threadIdx.x;
    const int wid  = tid >> 5;
    const int lane = tid & 31;
    const int g    = lane >> 2;
    const int t4   = lane & 3;
    const int lane15 = lane & 15;
    // lanes 0-15 fetch hi weights, lanes 16-31 the lo copy (ldmatrix.x4)
    const uint32_t bufb = smb + ((lane & 16) ? WLO : WHI);

    // ---- weight prep: bf16 hi/lo, SW128 swizzled [k][n] rows of 128B ----
    for (int e = tid; e < 10240; e += TPB) {
        const float* src; int rel, rb;
        if (e < 2048)      { src = W1; rel = e;        rb = 0;  }
        else if (e < 6144) { src = W2; rel = e - 2048; rb = 32; }
        else               { src = W3; rel = e - 6144; rb = 96; }
        int k = rel >> 6, n = rel & 63;
        float w = __ldg(src + rel);
        __nv_bfloat16 h = __float2bfloat16(w);
        float hf = __bfloat162float(h);
        __nv_bfloat16 l = __float2bfloat16(w - hf);
        uint32_t off = SWZ((uint32_t)((rb + k) * 128 + n * 2));
        *(__nv_bfloat16*)(sm + WHI + off) = h;
        *(__nv_bfloat16*)(sm + WLO + off) = l;
    }
    float* bias = (float*)(sm + BIAS_O);
    if (tid < 64) {
        bias[tid]       = __ldg(b1 + tid);
        bias[64 + tid]  = __ldg(b2 + tid);
        bias[128 + tid] = __ldg(b3 + tid);
    }
    __syncthreads();

    float* ss = (float*)(sm + SS_OFF);
    float* ts = (float*)(sm + TS_OFF);

    const int ntiles = nrows / ROWS_PER_CTA;

    for (int tile = blockIdx.x; tile < ntiles; tile += gridDim.x) {
        const float* xb = x + (size_t)tile * ROWS_PER_CTA * 64;

        uint32_t Ah[2][4][4], Al[2][4][4];
        float C[2][8][4];

        // ---- layer-1 A fragments straight from global (cin = even cols) ----
#pragma unroll
        for (int mt = 0; mt < 2; mt++) {
            int r0 = wid * 32 + mt * 16 + g;
            int r1 = r0 + 8;
#pragma unroll
            for (int s = 0; s < 2; s++) {
                const float4* p0 = (const float4*)(xb + r0 * 64 + s * 32) + t4;
                const float4* p1 = (const float4*)(xb + r1 * 64 + s * 32) + t4;
                float4 f0 = __ldg(p0);
                float4 f1 = __ldg(p0 + 4);
                float4 f2 = __ldg(p1);
                float4 f3 = __ldg(p1 + 4);
                split2(f0.x, f0.z, Ah[mt][s][0], Al[mt][s][0]);
                split2(f2.x, f2.z, Ah[mt][s][1], Al[mt][s][1]);
                split2(f1.x, f1.z, Ah[mt][s][2], Al[mt][s][2]);
                split2(f3.x, f3.z, Ah[mt][s][3], Al[mt][s][3]);
            }
        }

        // ---- 3 GEMM layers ----
        run_layer<2>(bufb, 0, lane15, Ah, Al, C);
        epi_relu_split(bias, t4, C, Ah, Al);
        run_layer<4>(bufb, 32, lane15, Ah, Al, C);
        epi_relu_split(bias + 64, t4, C, Ah, Al);
        run_layer<4>(bufb, 96, lane15, Ah, Al, C);

        // ---- layer-3 epilogue: s=tanh(st[:32]) -> ss, t=st[32:] -> ts ----
#pragma unroll
        for (int mt = 0; mt < 2; mt++) {
            int r0 = wid * 32 + mt * 16 + g;
#pragma unroll
            for (int j = 0; j < 8; j++) {
                int cs = 8 * (j & 3) + 2 * t4;
                float b0 = bias[128 + 8 * j + 2 * t4];
                float b1 = bias[128 + 8 * j + 2 * t4 + 1];
                float v0 = C[mt][j][0] + b0;
                float v1 = C[mt][j][1] + b1;
                float v2 = C[mt][j][2] + b0;
                float v3 = C[mt][j][3] + b1;
                if (j < 4) {
                    v0 = 1.0f - __fdividef(2.0f, __expf(2.0f * v0) + 1.0f);
                    v1 = 1.0f - __fdividef(2.0f, __expf(2.0f * v1) + 1.0f);
                    v2 = 1.0f - __fdividef(2.0f, __expf(2.0f * v2) + 1.0f);
                    v3 = 1.0f - __fdividef(2.0f, __expf(2.0f * v3) + 1.0f);
                    ss[r0 * 33 + cs]           = v0;
                    ss[r0 * 33 + cs + 1]       = v1;
                    ss[(r0 + 8) * 33 + cs]     = v2;
                    ss[(r0 + 8) * 33 + cs + 1] = v3;
                } else {
                    ts[r0 * 33 + cs]           = v0;
                    ts[r0 * 33 + cs + 1]       = v1;
                    ts[(r0 + 8) * 33 + cs]     = v2;
                    ts[(r0 + 8) * 33 + cs + 1] = v3;
                }
            }
        }
        __syncthreads();

        // ---- coalesced output pass ----
        {
            const float4* xt = (const float4*)xb;
            float4* oy = (float4*)out + (size_t)tile * (ROWS_PER_CTA * 16);
#pragma unroll
            for (int it = 0; it < 16; it++) {
                int f = it * TPB + tid;
                int row = f >> 4, q = f & 15;
                float4 v = __ldg(xt + f);
                float s0 = ss[row * 33 + 2 * q];
                float s1 = ss[row * 33 + 2 * q + 1];
                float t0 = ts[row * 33 + 2 * q];
                float t1 = ts[row * 33 + 2 * q + 1];
                v.y = fmaf(v.y, __expf(s0), t0);
                v.w = fmaf(v.w, __expf(s1), t1);
                oy[f] = v;
            }
            float4* os = (float4*)(out + (size_t)nrows * 64) + (size_t)tile * (ROWS_PER_CTA * 8);
#pragma unroll
            for (int it = 0; it < 8; it++) {
                int f = it * TPB + tid;
                int row = f >> 3, c4 = (f & 7) * 4;
                os[f] = make_float4(ss[row * 33 + c4],     ss[row * 33 + c4 + 1],
                                    ss[row * 33 + c4 + 2], ss[row * 33 + c4 + 3]);
            }
        }
        __syncthreads();   // staging reused next tile
    }
}

extern "C" void kernel_launch(void* const* d_in, const int* in_sizes, int n_in,
                              void* d_out, int out_size) {
    const float* x  = (const float*)d_in[0];
    const float* W1 = (const float*)d_in[1];
    const float* b1 = (const float*)d_in[2];
    const float* W2 = (const float*)d_in[3];
    const float* b2 = (const float*)d_in[4];
    const float* W3 = (const float*)d_in[5];
    const float* b3 = (const float*)d_in[6];
    float* out = (float*)d_out;

    const int nrows = in_sizes[0] / 64;
    const int ntiles = nrows / ROWS_PER_CTA;
    int grid = 444;
    if (grid > ntiles) grid = ntiles;

    static int smem_set = 0;
    if (!smem_set) {
        cudaFuncSetAttribute(affine_coupling_hmma,
                             cudaFuncAttributeMaxDynamicSharedMemorySize, SMEM_BYTES);
        smem_set = 1;
    }
    affine_coupling_hmma<<<grid, TPB, SMEM_BYTES>>>(x, W1, b1, W2, b2, W3, b3, out, nrows);
}

// round 6
// speedup vs baseline: 3.1489x; 1.0775x over previous
#include <cuda_runtime.h>
#include <cuda_bf16.h>
#include <cstdint>

// AffineCouplingLayer via legacy tensor pipe (mma.sync bf16, sm_100-safe).
// B=524288 rows, D=64. cin = even cols (32).
//   h1 = relu(cin@W1+b1); h2 = relu(h1@W2+b2); st = h2@W3+b3
//   s = tanh(st[:32]); y = x with odd cols = x_odd*exp(s)+t
// out = [ y (B*64 f32) | s (B*32 f32) ]
//
// Per-warp tile M=16 (one m16), N=64 (8 x n8); 8 warps/CTA -> 128 rows/CTA;
// 2 CTAs/SM (16 warps). Activations register-resident across layers.
// Weights bf16 hi/lo split in swizzled SMEM; ldmatrix.x4.trans fetches
// {bh0,bh1,bl0,bl1} in one op (lanes 0-15 -> WHI, 16-31 -> WLO).
// 3 mma products per GEMM: Ah@Bh + Al@Bh + Ah@Bl (err ~2^-17).
// Staging: sst[row][q] = {s2q, s2q+1, t2q, t2q+1} (float4) for the output pass.
// Next tile's x prefetched into regs before the output pass.

#define TPB          256
#define ROWS_PER_CTA 128

// ---- SMEM layout (bytes) ----
#define WHI     0            // 160 rows * 128B
#define WLO     20480
#define BIAS_O  40960        // 192 f32
#define SST_OFF 41728        // 128 * 17 * 16B = 34816
#define SMEM_BYTES 76544

#define SWZ(o) ((o) ^ (((o) >> 3) & 0x70))

static __device__ __forceinline__ uint32_t smem_u32_of(const void* p) {
    uint32_t a;
    asm("{ .reg .u64 t; cvta.to.shared.u64 t, %1; cvt.u32.u64 %0, t; }" : "=r"(a) : "l"(p));
    return a;
}

static __device__ __forceinline__ uint32_t pack_bf16(float lo, float hi) {
    uint32_t r;
    asm("cvt.rn.bf16x2.f32 %0, %1, %2;" : "=r"(r) : "f"(hi), "f"(lo));
    return r;
}

static __device__ __forceinline__ void split2(float u, float v, uint32_t& h, uint32_t& l) {
    h = pack_bf16(u, v);
    float hu = __uint_as_float(h << 16);
    float hv = __uint_as_float(h & 0xFFFF0000u);
    l = pack_bf16(u - hu, v - hv);
}

static __device__ __forceinline__ void mma16816(float* c, const uint32_t* a,
                                                uint32_t b0, uint32_t b1) {
    asm volatile(
        "mma.sync.aligned.m16n8k16.row.col.f32.bf16.bf16.f32 "
        "{%0,%1,%2,%3}, {%4,%5,%6,%7}, {%8,%9}, {%0,%1,%2,%3};"
        : "+f"(c[0]), "+f"(c[1]), "+f"(c[2]), "+f"(c[3])
        : "r"(a[0]), "r"(a[1]), "r"(a[2]), "r"(a[3]), "r"(b0), "r"(b1));
}

static __device__ __forceinline__ void ldsm4t(uint32_t addr, uint32_t& bh0, uint32_t& bh1,
                                              uint32_t& bl0, uint32_t& bl1) {
    asm volatile("ldmatrix.sync.aligned.m8n8.x4.trans.shared.b16 {%0,%1,%2,%3}, [%4];"
                 : "=r"(bh0), "=r"(bh1), "=r"(bl0), "=r"(bl1) : "r"(addr));
}

// One GEMM layer: C[8][4] = (Ah+Al) @ (Bh+Bl), dropping Al@Bl.
// j-pairs interleaved: two independent accumulator chains in flight.
template <int KS>
static __device__ __forceinline__ void run_layer(uint32_t bufb, int row_rb, int lane15,
                                                 const uint32_t Ah[4][4],
                                                 const uint32_t Al[4][4],
                                                 float C[8][4]) {
#pragma unroll
    for (int j = 0; j < 8; j++)
#pragma unroll
        for (int q = 0; q < 4; q++) C[j][q] = 0.0f;

#pragma unroll
    for (int s = 0; s < KS; s++) {
        int rowc = row_rb + s * 16 + lane15;
        uint32_t base = bufb + (uint32_t)rowc * 128;
        uint32_t x7 = (uint32_t)(rowc & 7);
#pragma unroll
        for (int jj = 0; jj < 4; jj++) {
            int j0 = 2 * jj, j1 = j0 + 1;
            uint32_t a0 = base + (((uint32_t)j0 ^ x7) << 4);
            uint32_t a1 = base + (((uint32_t)j1 ^ x7) << 4);
            uint32_t bh00, bh01, bl00, bl01, bh10, bh11, bl10, bl11;
            ldsm4t(a0, bh00, bh01, bl00, bl01);
            ldsm4t(a1, bh10, bh11, bl10, bl11);
            mma16816(C[j0], Ah[s], bh00, bh01);
            mma16816(C[j1], Ah[s], bh10, bh11);
            mma16816(C[j0], Al[s], bh00, bh01);
            mma16816(C[j1], Al[s], bh10, bh11);
            mma16816(C[j0], Ah[s], bl00, bl01);
            mma16816(C[j1], Ah[s], bl10, bl11);
        }
    }
}

// bias + relu + hi/lo split: C (this layer) -> A fragments (next layer)
static __device__ __forceinline__ void epi_relu_split(const float* bias, int t4,
                                                      const float C[8][4],
                                                      uint32_t Ah[4][4],
                                                      uint32_t Al[4][4]) {
#pragma unroll
    for (int j = 0; j < 8; j++) {
        float b0 = bias[8 * j + 2 * t4];
        float b1 = bias[8 * j + 2 * t4 + 1];
        float v0 = fmaxf(C[j][0] + b0, 0.0f);
        float v1 = fmaxf(C[j][1] + b1, 0.0f);
        float v2 = fmaxf(C[j][2] + b0, 0.0f);
        float v3 = fmaxf(C[j][3] + b1, 0.0f);
        int s = j >> 1;
        int fi = (j & 1) * 2;
        split2(v0, v1, Ah[s][fi],     Al[s][fi]);
        split2(v2, v3, Ah[s][fi + 1], Al[s][fi + 1]);
    }
}

// Gather layer-1 A fragments from 8 prefetched float4 (even cols of x).
static __device__ __forceinline__ void frags_from_x(const float4 px[8],
                                                    uint32_t Ah[4][4], uint32_t Al[4][4]) {
#pragma unroll
    for (int s = 0; s < 2; s++) {
        const float4& f0 = px[s * 4 + 0];   // row r0,   k-lo
        const float4& f1 = px[s * 4 + 1];   // row r0,   k-hi
        const float4& f2 = px[s * 4 + 2];   // row r0+8, k-lo
        const float4& f3 = px[s * 4 + 3];   // row r0+8, k-hi
        split2(f0.x, f0.z, Ah[s][0], Al[s][0]);
        split2(f2.x, f2.z, Ah[s][1], Al[s][1]);
        split2(f1.x, f1.z, Ah[s][2], Al[s][2]);
        split2(f3.x, f3.z, Ah[s][3], Al[s][3]);
    }
}

static __device__ __forceinline__ void load_px(const float* xb, int r0, int t4, float4 px[8]) {
#pragma unroll
    for (int s = 0; s < 2; s++) {
        const float4* p0 = (const float4*)(xb + r0 * 64 + s * 32) + t4;
        const float4* p1 = (const float4*)(xb + (r0 + 8) * 64 + s * 32) + t4;
        px[s * 4 + 0] = __ldg(p0);
        px[s * 4 + 1] = __ldg(p0 + 4);
        px[s * 4 + 2] = __ldg(p1);
        px[s * 4 + 3] = __ldg(p1 + 4);
    }
}

__global__ void __launch_bounds__(TPB, 2)
affine_coupling_hmma(const float* __restrict__ x,
                     const float* __restrict__ W1, const float* __restrict__ b1,
                     const float* __restrict__ W2, const float* __restrict__ b2,
                     const float* __restrict__ W3, const float* __restrict__ b3,
                     float* __restrict__ out, int nrows) {
    extern __shared__ char sm[];
    const uint32_t smb = smem_u32_of(sm);

    const int tid  = threadIdx.x;
    const int wid  = tid >> 5;
    const int lane = tid & 31;
    const int g    = lane >> 2;
    const int t4   = lane & 3;
    const int lane15 = lane & 15;
    const uint32_t bufb = smb + ((lane & 16) ? WLO : WHI);
    const int r0 = wid * 16 + g;              // first owned row in epilogues

    // ---- weight prep: bf16 hi/lo, SW128 swizzled [k][n] rows of 128B ----
    for (int e = tid; e < 10240; e += TPB) {
        const float* src; int rel, rb;
        if (e < 2048)      { src = W1; rel = e;        rb = 0;  }
        else if (e < 6144) { src = W2; rel = e - 2048; rb = 32; }
        else               { src = W3; rel = e - 6144; rb = 96; }
        int k = rel >> 6, n = rel & 63;
        float w = __ldg(src + rel);
        __nv_bfloat16 h = __float2bfloat16(w);
        float hf = __bfloat162float(h);
        __nv_bfloat16 l = __float2bfloat16(w - hf);
        uint32_t off = SWZ((uint32_t)((rb + k) * 128 + n * 2));
        *(__nv_bfloat16*)(sm + WHI + off) = h;
        *(__nv_bfloat16*)(sm + WLO + off) = l;
    }
    float* bias = (float*)(sm + BIAS_O);
    if (tid < 64) {
        bias[tid]       = __ldg(b1 + tid);
        bias[64 + tid]  = __ldg(b2 + tid);
        bias[128 + tid] = __ldg(b3 + tid);
    }
    __syncthreads();

    const int ntiles = nrows / ROWS_PER_CTA;
    int tile = blockIdx.x;
    if (tile >= ntiles) return;

    float4 px[8];
    load_px(x + (size_t)tile * ROWS_PER_CTA * 64, r0, t4, px);

    for (; tile < ntiles; tile += gridDim.x) {
        const float* xb = x + (size_t)tile * ROWS_PER_CTA * 64;

        uint32_t Ah[4][4], Al[4][4];
        float C[8][4];

        frags_from_x(px, Ah, Al);

        // ---- 3 GEMM layers ----
        run_layer<2>(bufb, 0, lane15, Ah, Al, C);
        epi_relu_split(bias, t4, C, Ah, Al);
        run_layer<4>(bufb, 32, lane15, Ah, Al, C);
        epi_relu_split(bias + 64, t4, C, Ah, Al);
        run_layer<4>(bufb, 96, lane15, Ah, Al, C);

        // ---- layer-3 epilogue -> sst staging {s0,s1,t0,t1} per col pair ----
#pragma unroll
        for (int j = 0; j < 8; j++) {
            float b0 = bias[128 + 8 * j + 2 * t4];
            float b1 = bias[128 + 8 * j + 2 * t4 + 1];
            float v0 = C[j][0] + b0;
            float v1 = C[j][1] + b1;
            float v2 = C[j][2] + b0;
            float v3 = C[j][3] + b1;
            int q = 4 * (j & 3) + t4;
            uint32_t off = (j < 4) ? 0u : 8u;
            if (j < 4) {
                v0 = 1.0f - __fdividef(2.0f, __expf(2.0f * v0) + 1.0f);
                v1 = 1.0f - __fdividef(2.0f, __expf(2.0f * v1) + 1.0f);
                v2 = 1.0f - __fdividef(2.0f, __expf(2.0f * v2) + 1.0f);
                v3 = 1.0f - __fdividef(2.0f, __expf(2.0f * v3) + 1.0f);
            }
            uint32_t a0 = smb + SST_OFF + (uint32_t)(r0 * 17 + q) * 16 + off;
            uint32_t a1 = smb + SST_OFF + (uint32_t)((r0 + 8) * 17 + q) * 16 + off;
            asm volatile("st.shared.v2.f32 [%0], {%1,%2};" :: "r"(a0), "f"(v0), "f"(v1) : "memory");
            asm volatile("st.shared.v2.f32 [%0], {%1,%2};" :: "r"(a1), "f"(v2), "f"(v3) : "memory");
        }

        // ---- prefetch next tile's x (hidden behind output pass) ----
        {
            int tn = tile + gridDim.x;
            if (tn >= ntiles) tn = tile;
            load_px(x + (size_t)tn * ROWS_PER_CTA * 64, r0, t4, px);
        }
        __syncthreads();

        // ---- coalesced output pass ----
        {
            const float4* xt = (const float4*)xb;
            float4* oy = (float4*)out + (size_t)tile * (ROWS_PER_CTA * 16);
#pragma unroll
            for (int it = 0; it < 8; it++) {
                int f = it * TPB + tid;
                int row = f >> 4, q = f & 15;
                float4 v = __ldg(xt + f);
                float4 st4;
                uint32_t ad = smb + SST_OFF + (uint32_t)(row * 17 + q) * 16;
                asm volatile("ld.shared.v4.f32 {%0,%1,%2,%3}, [%4];"
                             : "=f"(st4.x), "=f"(st4.y), "=f"(st4.z), "=f"(st4.w) : "r"(ad));
                v.y = fmaf(v.y, __expf(st4.x), st4.z);
                v.w = fmaf(v.w, __expf(st4.y), st4.w);
                oy[f] = v;
            }
            float4* os = (float4*)(out + (size_t)nrows * 64) + (size_t)tile * (ROWS_PER_CTA * 8);
#pragma unroll
            for (int it = 0; it < 4; it++) {
                int f = it * TPB + tid;
                int row = f >> 3, c = f & 7;
                uint32_t ad = smb + SST_OFF + (uint32_t)(row * 17 + 2 * c) * 16;
                float s0, s1, s2, s3;
                asm volatile("ld.shared.v2.f32 {%0,%1}, [%2];" : "=f"(s0), "=f"(s1) : "r"(ad));
                asm volatile("ld.shared.v2.f32 {%0,%1}, [%2];" : "=f"(s2), "=f"(s3) : "r"(ad + 16));
                os[f] = make_float4(s0, s1, s2, s3);
            }
        }
        __syncthreads();   // staging reused next tile
    }
}

extern "C" void kernel_launch(void* const* d_in, const int* in_sizes, int n_in,
                              void* d_out, int out_size) {
    const float* x  = (const float*)d_in[0];
    const float* W1 = (const float*)d_in[1];
    const float* b1 = (const float*)d_in[2];
    const float* W2 = (const float*)d_in[3];
    const float* b2 = (const float*)d_in[4];
    const float* W3 = (const float*)d_in[5];
    const float* b3 = (const float*)d_in[6];
    float* out = (float*)d_out;

    const int nrows = in_sizes[0] / 64;
    const int ntiles = nrows / ROWS_PER_CTA;
    int grid = 296;                      // 2 CTAs/SM * 148 SMs
    if (grid > ntiles) grid = ntiles;

    static int smem_set = 0;
    if (!smem_set) {
        cudaFuncSetAttribute(affine_coupling_hmma,
                             cudaFuncAttributeMaxDynamicSharedMemorySize, SMEM_BYTES);
        smem_set = 1;
    }
    affine_coupling_hmma<<<grid, TPB, SMEM_BYTES>>>(x, W1, b1, W2, b2, W3, b3, out, nrows);
}

// round 8
// speedup vs baseline: 3.5857x; 1.1387x over previous
#include <cuda_runtime.h>
#include <cuda_bf16.h>
#include <cstdint>

// AffineCouplingLayer via legacy tensor pipe (mma.sync bf16, sm_100-safe).
// B=524288 rows, D=64. cin = even cols (32).
//   h1 = relu(cin@W1+b1); h2 = relu(h1@W2+b2); st = h2@W3+b3
//   s = tanh(st[:32]); y = x with odd cols = x_odd*exp(s)+t
// out = [ y (B*64 f32) | s (B*32 f32) ]
//
// Per-warp tile M=16, N=64; 8 warps/CTA -> 128 rows/CTA; 2 CTAs/SM.
// Activations register-resident across layers (C frag == next A frag).
// Weights bf16 hi/lo split in swizzled SMEM; one ldmatrix.x4.trans per
// 16B chunk fetches {bh0,bh1,bl0,bl1} (lanes 0-15 -> WHI, 16-31 -> WLO).
// 3 mma products per GEMM: Ah@Bh + Al@Bh + Ah@Bl (err ~2^-17).
//
// REGISTER-DIRECT EPILOGUE: the thread that loaded x[row][4q..4q+3] (px)
// owns exactly s[2q..2q+1] / t[2q..2q+1] in its layer-3 C fragments, so y
// is computed and stored straight from registers (no x re-read, no t
// staging). Only s goes through smem, for a coalesced s-output block.
// Staging row stride = 34 floats (EVEN -> all v2.f32 accesses 8B-aligned).

#define TPB          256
#define ROWS_PER_CTA 128
#define SS_STRIDE    34

// ---- SMEM layout (bytes) ----
#define WHI     0            // 160 rows * 128B
#define WLO     20480
#define BIAS_O  40960        // 192 f32
#define SS_OFF  41728        // 128 * 34 f32 = 17408
#define SMEM_BYTES 59136

#define SWZ(o) ((o) ^ (((o) >> 3) & 0x70))

static __device__ __forceinline__ uint32_t smem_u32_of(const void* p) {
    uint32_t a;
    asm("{ .reg .u64 t; cvta.to.shared.u64 t, %1; cvt.u32.u64 %0, t; }" : "=r"(a) : "l"(p));
    return a;
}

static __device__ __forceinline__ uint32_t pack_bf16(float lo, float hi) {
    uint32_t r;
    asm("cvt.rn.bf16x2.f32 %0, %1, %2;" : "=r"(r) : "f"(hi), "f"(lo));
    return r;
}

static __device__ __forceinline__ void split2(float u, float v, uint32_t& h, uint32_t& l) {
    h = pack_bf16(u, v);
    float hu = __uint_as_float(h << 16);
    float hv = __uint_as_float(h & 0xFFFF0000u);
    l = pack_bf16(u - hu, v - hv);
}

static __device__ __forceinline__ float tanh_fast(float v) {
    return 1.0f - __fdividef(2.0f, __expf(2.0f * v) + 1.0f);
}

static __device__ __forceinline__ void mma16816(float* c, const uint32_t* a,
                                                uint32_t b0, uint32_t b1) {
    asm volatile(
        "mma.sync.aligned.m16n8k16.row.col.f32.bf16.bf16.f32 "
        "{%0,%1,%2,%3}, {%4,%5,%6,%7}, {%8,%9}, {%0,%1,%2,%3};"
        : "+f"(c[0]), "+f"(c[1]), "+f"(c[2]), "+f"(c[3])
        : "r"(a[0]), "r"(a[1]), "r"(a[2]), "r"(a[3]), "r"(b0), "r"(b1));
}

static __device__ __forceinline__ void ldsm4t(uint32_t addr, uint32_t& bh0, uint32_t& bh1,
                                              uint32_t& bl0, uint32_t& bl1) {
    asm volatile("ldmatrix.sync.aligned.m8n8.x4.trans.shared.b16 {%0,%1,%2,%3}, [%4];"
                 : "=r"(bh0), "=r"(bh1), "=r"(bl0), "=r"(bl1) : "r"(addr));
}

// One GEMM layer: C[8][4] = (Ah+Al) @ (Bh+Bl), dropping Al@Bl.
template <int KS>
static __device__ __forceinline__ void run_layer(uint32_t bufb, int row_rb, int lane15,
                                                 const uint32_t Ah[4][4],
                                                 const uint32_t Al[4][4],
                                                 float C[8][4]) {
#pragma unroll
    for (int j = 0; j < 8; j++)
#pragma unroll
        for (int q = 0; q < 4; q++) C[j][q] = 0.0f;

#pragma unroll
    for (int s = 0; s < KS; s++) {
        int rowc = row_rb + s * 16 + lane15;
        uint32_t base = bufb + (uint32_t)rowc * 128;
        uint32_t x7 = (uint32_t)(rowc & 7);
#pragma unroll
        for (int jj = 0; jj < 4; jj++) {
            int j0 = 2 * jj, j1 = j0 + 1;
            uint32_t a0 = base + (((uint32_t)j0 ^ x7) << 4);
            uint32_t a1 = base + (((uint32_t)j1 ^ x7) << 4);
            uint32_t bh00, bh01, bl00, bl01, bh10, bh11, bl10, bl11;
            ldsm4t(a0, bh00, bh01, bl00, bl01);
            ldsm4t(a1, bh10, bh11, bl10, bl11);
            mma16816(C[j0], Ah[s], bh00, bh01);
            mma16816(C[j1], Ah[s], bh10, bh11);
            mma16816(C[j0], Al[s], bh00, bh01);
            mma16816(C[j1], Al[s], bh10, bh11);
            mma16816(C[j0], Ah[s], bl00, bl01);
            mma16816(C[j1], Ah[s], bl10, bl11);
        }
    }
}

// bias + relu + hi/lo split: C (this layer) -> A fragments (next layer)
static __device__ __forceinline__ void epi_relu_split(const float* bias, int t4,
                                                      const float C[8][4],
                                                      uint32_t Ah[4][4],
                                                      uint32_t Al[4][4]) {
#pragma unroll
    for (int j = 0; j < 8; j++) {
        float b0 = bias[8 * j + 2 * t4];
        float b1 = bias[8 * j + 2 * t4 + 1];
        float v0 = fmaxf(C[j][0] + b0, 0.0f);
        float v1 = fmaxf(C[j][1] + b1, 0.0f);
        float v2 = fmaxf(C[j][2] + b0, 0.0f);
        float v3 = fmaxf(C[j][3] + b1, 0.0f);
        int s = j >> 1;
        int fi = (j & 1) * 2;
        split2(v0, v1, Ah[s][fi],     Al[s][fi]);
        split2(v2, v3, Ah[s][fi + 1], Al[s][fi + 1]);
    }
}

// Gather layer-1 A fragments from the 8 live px float4 (even cols of x).
static __device__ __forceinline__ void frags_from_x(const float4 px[8],
                                                    uint32_t Ah[4][4], uint32_t Al[4][4]) {
#pragma unroll
    for (int s = 0; s < 2; s++) {
        const float4& f0 = px[s * 4 + 0];   // row r0,   col-half u=0
        const float4& f1 = px[s * 4 + 1];   // row r0,   col-half u=1
        const float4& f2 = px[s * 4 + 2];   // row r0+8, u=0
        const float4& f3 = px[s * 4 + 3];   // row r0+8, u=1
        split2(f0.x, f0.z, Ah[s][0], Al[s][0]);
        split2(f2.x, f2.z, Ah[s][1], Al[s][1]);
        split2(f1.x, f1.z, Ah[s][2], Al[s][2]);
        split2(f3.x, f3.z, Ah[s][3], Al[s][3]);
    }
}

static __device__ __forceinline__ void load_px(const float* xb, int r0, int t4, float4 px[8]) {
#pragma unroll
    for (int s = 0; s < 2; s++) {
        const float4* p0 = (const float4*)(xb + r0 * 64 + s * 32) + t4;
        const float4* p1 = (const float4*)(xb + (r0 + 8) * 64 + s * 32) + t4;
        px[s * 4 + 0] = __ldg(p0);
        px[s * 4 + 1] = __ldg(p0 + 4);
        px[s * 4 + 2] = __ldg(p1);
        px[s * 4 + 3] = __ldg(p1 + 4);
    }
}

__global__ void __launch_bounds__(TPB, 2)
affine_coupling_hmma(const float* __restrict__ x,
                     const float* __restrict__ W1, const float* __restrict__ b1,
                     const float* __restrict__ W2, const float* __restrict__ b2,
                     const float* __restrict__ W3, const float* __restrict__ b3,
                     float* __restrict__ out, int nrows) {
    extern __shared__ char sm[];
    const uint32_t smb = smem_u32_of(sm);

    const int tid  = threadIdx.x;
    const int wid  = tid >> 5;
    const int lane = tid & 31;
    const int g    = lane >> 2;
    const int t4   = lane & 3;
    const int lane15 = lane & 15;
    const uint32_t bufb = smb + ((lane & 16) ? WLO : WHI);
    const int r0 = wid * 16 + g;              // first owned row

    // ---- weight prep: bf16 hi/lo, SW128 swizzled [k][n] rows of 128B ----
    for (int e = tid; e < 10240; e += TPB) {
        const float* src; int rel, rb;
        if (e < 2048)      { src = W1; rel = e;        rb = 0;  }
        else if (e < 6144) { src = W2; rel = e - 2048; rb = 32; }
        else               { src = W3; rel = e - 6144; rb = 96; }
        int k = rel >> 6, n = rel & 63;
        float w = __ldg(src + rel);
        __nv_bfloat16 h = __float2bfloat16(w);
        float hf = __bfloat162float(h);
        __nv_bfloat16 l = __float2bfloat16(w - hf);
        uint32_t off = SWZ((uint32_t)((rb + k) * 128 + n * 2));
        *(__nv_bfloat16*)(sm + WHI + off) = h;
        *(__nv_bfloat16*)(sm + WLO + off) = l;
    }
    float* bias = (float*)(sm + BIAS_O);
    if (tid < 64) {
        bias[tid]       = __ldg(b1 + tid);
        bias[64 + tid]  = __ldg(b2 + tid);
        bias[128 + tid] = __ldg(b3 + tid);
    }
    __syncthreads();

    const int ntiles = nrows / ROWS_PER_CTA;

    for (int tile = blockIdx.x; tile < ntiles; tile += gridDim.x) {
        const float* xb = x + (size_t)tile * ROWS_PER_CTA * 64;

        float4 px[8];
        load_px(xb, r0, t4, px);

        uint32_t Ah[4][4], Al[4][4];
        float C[8][4];

        frags_from_x(px, Ah, Al);

        // ---- 3 GEMM layers ----
        run_layer<2>(bufb, 0, lane15, Ah, Al, C);
        epi_relu_split(bias, t4, C, Ah, Al);
        run_layer<4>(bufb, 32, lane15, Ah, Al, C);
        epi_relu_split(bias + 64, t4, C, Ah, Al);
        run_layer<4>(bufb, 96, lane15, Ah, Al, C);

        // ---- register-direct epilogue: y straight from px + C frags ----
        // px block (s,u): odd cols -> sigma = 16s+8u+2*t4 -> s in C[2s+u],
        // t in C[2s+u+4], same lane, rows r0 (frag 0,1) / r0+8 (frag 2,3).
        {
            const float* b3s = bias + 128;
            float4* oy = (float4*)out + (size_t)tile * (ROWS_PER_CTA * 16);
#pragma unroll
            for (int s = 0; s < 2; s++) {
#pragma unroll
                for (int u = 0; u < 2; u++) {
                    int js = 2 * s + u, jt = js + 4;
                    int sig = 16 * s + 8 * u + 2 * t4;
                    float bs0 = b3s[sig], bs1 = b3s[sig + 1];
                    float bt0 = b3s[32 + sig], bt1 = b3s[32 + sig + 1];

                    float sa0 = tanh_fast(C[js][0] + bs0);
                    float sb0 = tanh_fast(C[js][1] + bs1);
                    float sa1 = tanh_fast(C[js][2] + bs0);
                    float sb1 = tanh_fast(C[js][3] + bs1);
                    float ta0 = C[jt][0] + bt0, tb0 = C[jt][1] + bt1;
                    float ta1 = C[jt][2] + bt0, tb1 = C[jt][3] + bt1;

                    // stage s for the coalesced s-output (stride 34 -> 8B aligned)
                    uint32_t a0 = smb + SS_OFF + (uint32_t)(r0 * SS_STRIDE + sig) * 4;
                    uint32_t a1 = smb + SS_OFF + (uint32_t)((r0 + 8) * SS_STRIDE + sig) * 4;
                    asm volatile("st.shared.v2.f32 [%0], {%1,%2};" :: "r"(a0), "f"(sa0), "f"(sb0) : "memory");
                    asm volatile("st.shared.v2.f32 [%0], {%1,%2};" :: "r"(a1), "f"(sa1), "f"(sb1) : "memory");

                    // y stores straight from registers
                    float4 v0 = px[4 * s + u];          // row r0
                    float4 v1 = px[4 * s + 2 + u];      // row r0+8
                    v0.y = fmaf(v0.y, __expf(sa0), ta0);
                    v0.w = fmaf(v0.w, __expf(sb0), tb0);
                    v1.y = fmaf(v1.y, __expf(sa1), ta1);
                    v1.w = fmaf(v1.w, __expf(sb1), tb1);
                    int c4 = (32 * s + 16 * u) >> 2;    // float4 col index base
                    oy[r0 * 16 + c4 + t4]       = v0;
                    oy[(r0 + 8) * 16 + c4 + t4] = v1;
                }
            }
        }
        __syncthreads();

        // ---- coalesced s-output (8B-aligned v2 loads) ----
        {
            float4* os = (float4*)(out + (size_t)nrows * 64) + (size_t)tile * (ROWS_PER_CTA * 8);
#pragma unroll
            for (int it = 0; it < 4; it++) {
                int f = it * TPB + tid;
                int row = f >> 3, c = (f & 7) * 4;
                uint32_t ad = smb + SS_OFF + (uint32_t)(row * SS_STRIDE + c) * 4;
                float s0, s1, s2, s3;
                asm volatile("ld.shared.v2.f32 {%0,%1}, [%2];" : "=f"(s0), "=f"(s1) : "r"(ad));
                asm volatile("ld.shared.v2.f32 {%0,%1}, [%2];" : "=f"(s2), "=f"(s3) : "r"(ad + 8));
                os[f] = make_float4(s0, s1, s2, s3);
            }
        }
        __syncthreads();   // staging reused next tile
    }
}

extern "C" void kernel_launch(void* const* d_in, const int* in_sizes, int n_in,
                              void* d_out, int out_size) {
    const float* x  = (const float*)d_in[0];
    const float* W1 = (const float*)d_in[1];
    const float* b1 = (const float*)d_in[2];
    const float* W2 = (const float*)d_in[3];
    const float* b2 = (const float*)d_in[4];
    const float* W3 = (const float*)d_in[5];
    const float* b3 = (const float*)d_in[6];
    float* out = (float*)d_out;

    const int nrows = in_sizes[0] / 64;
    const int ntiles = nrows / ROWS_PER_CTA;
    int grid = 296;                      // 2 CTAs/SM * 148 SMs
    if (grid > ntiles) grid = ntiles;

    static int smem_set = 0;
    if (!smem_set) {
        cudaFuncSetAttribute(affine_coupling_hmma,
                             cudaFuncAttributeMaxDynamicSharedMemorySize, SMEM_BYTES);
        smem_set = 1;
    }
    affine_coupling_hmma<<<grid, TPB, SMEM_BYTES>>>(x, W1, b1, W2, b2, W3, b3, out, nrows);
}

// round 9
// speedup vs baseline: 3.8508x; 1.0739x over previous
#include <cuda_runtime.h>
#include <cuda_bf16.h>
#include <cstdint>

// AffineCouplingLayer via legacy tensor pipe (mma.sync bf16, sm_100-safe).
// B=524288 rows, D=64. cin = even cols (32).
//   h1 = relu(cin@W1+b1); h2 = relu(h1@W2+b2); st = h2@W3+b3
//   s = tanh(st[:32]); y = x with odd cols = x_odd*exp(s)+t
// out = [ y (B*64 f32) | s (B*32 f32) ]
//
// Per-warp tile M=16, N=64; 8 warps/CTA -> 128 rows/CTA; 2 CTAs/SM.
// Activations register-resident across layers (C frag == next A frag).
// Weights bf16 hi/lo split in swizzled SMEM; one ldmatrix.x4.trans per
// 16B chunk fetches {bh0,bh1,bl0,bl1} (lanes 0-15 -> WHI, 16-31 -> WLO).
// 3 mma products per GEMM: Ah@Bh + Al@Bh + Ah@Bl (err ~2^-17).
//
// BARRIER-FREE TILE LOOP: y AND s are both written straight from registers
// (fragment ownership: the thread holding x[row][4q..4q+3] owns s/t[2q,2q+1]
// in its layer-3 C frags; for fixed (s,u) a warp's t4 lanes cover a 32B-
// aligned contiguous chunk of the s row -> 1 sector per chunk). No smem
// staging, no __syncthreads in the loop -> warps free-run and their GEMM /
// epilogue phases overlap across the SM.

#define TPB          256
#define ROWS_PER_CTA 128

// ---- SMEM layout (bytes) ----
#define WHI     0            // 160 rows * 128B
#define WLO     20480
#define BIAS_O  40960        // 192 f32
#define SMEM_BYTES 41728

#define SWZ(o) ((o) ^ (((o) >> 3) & 0x70))

static __device__ __forceinline__ uint32_t smem_u32_of(const void* p) {
    uint32_t a;
    asm("{ .reg .u64 t; cvta.to.shared.u64 t, %1; cvt.u32.u64 %0, t; }" : "=r"(a) : "l"(p));
    return a;
}

static __device__ __forceinline__ uint32_t pack_bf16(float lo, float hi) {
    uint32_t r;
    asm("cvt.rn.bf16x2.f32 %0, %1, %2;" : "=r"(r) : "f"(hi), "f"(lo));
    return r;
}

static __device__ __forceinline__ void split2(float u, float v, uint32_t& h, uint32_t& l) {
    h = pack_bf16(u, v);
    float hu = __uint_as_float(h << 16);
    float hv = __uint_as_float(h & 0xFFFF0000u);
    l = pack_bf16(u - hu, v - hv);
}

static __device__ __forceinline__ float tanh_fast(float v) {
    return 1.0f - __fdividef(2.0f, __expf(2.0f * v) + 1.0f);
}

static __device__ __forceinline__ void mma16816(float* c, const uint32_t* a,
                                                uint32_t b0, uint32_t b1) {
    asm volatile(
        "mma.sync.aligned.m16n8k16.row.col.f32.bf16.bf16.f32 "
        "{%0,%1,%2,%3}, {%4,%5,%6,%7}, {%8,%9}, {%0,%1,%2,%3};"
        : "+f"(c[0]), "+f"(c[1]), "+f"(c[2]), "+f"(c[3])
        : "r"(a[0]), "r"(a[1]), "r"(a[2]), "r"(a[3]), "r"(b0), "r"(b1));
}

static __device__ __forceinline__ void ldsm4t(uint32_t addr, uint32_t& bh0, uint32_t& bh1,
                                              uint32_t& bl0, uint32_t& bl1) {
    asm volatile("ldmatrix.sync.aligned.m8n8.x4.trans.shared.b16 {%0,%1,%2,%3}, [%4];"
                 : "=r"(bh0), "=r"(bh1), "=r"(bl0), "=r"(bl1) : "r"(addr));
}

// One GEMM layer: C[8][4] = (Ah+Al) @ (Bh+Bl), dropping Al@Bl.
template <int KS>
static __device__ __forceinline__ void run_layer(uint32_t bufb, int row_rb, int lane15,
                                                 const uint32_t Ah[4][4],
                                                 const uint32_t Al[4][4],
                                                 float C[8][4]) {
#pragma unroll
    for (int j = 0; j < 8; j++)
#pragma unroll
        for (int q = 0; q < 4; q++) C[j][q] = 0.0f;

#pragma unroll
    for (int s = 0; s < KS; s++) {
        int rowc = row_rb + s * 16 + lane15;
        uint32_t base = bufb + (uint32_t)rowc * 128;
        uint32_t x7 = (uint32_t)(rowc & 7);
#pragma unroll
        for (int jj = 0; jj < 4; jj++) {
            int j0 = 2 * jj, j1 = j0 + 1;
            uint32_t a0 = base + (((uint32_t)j0 ^ x7) << 4);
            uint32_t a1 = base + (((uint32_t)j1 ^ x7) << 4);
            uint32_t bh00, bh01, bl00, bl01, bh10, bh11, bl10, bl11;
            ldsm4t(a0, bh00, bh01, bl00, bl01);
            ldsm4t(a1, bh10, bh11, bl10, bl11);
            mma16816(C[j0], Ah[s], bh00, bh01);
            mma16816(C[j1], Ah[s], bh10, bh11);
            mma16816(C[j0], Al[s], bh00, bh01);
            mma16816(C[j1], Al[s], bh10, bh11);
            mma16816(C[j0], Ah[s], bl00, bl01);
            mma16816(C[j1], Ah[s], bl10, bl11);
        }
    }
}

// bias + relu + hi/lo split: C (this layer) -> A fragments (next layer)
static __device__ __forceinline__ void epi_relu_split(const float* bias, int t4,
                                                      const float C[8][4],
                                                      uint32_t Ah[4][4],
                                                      uint32_t Al[4][4]) {
#pragma unroll
    for (int j = 0; j < 8; j++) {
        float b0 = bias[8 * j + 2 * t4];
        float b1 = bias[8 * j + 2 * t4 + 1];
        float v0 = fmaxf(C[j][0] + b0, 0.0f);
        float v1 = fmaxf(C[j][1] + b1, 0.0f);
        float v2 = fmaxf(C[j][2] + b0, 0.0f);
        float v3 = fmaxf(C[j][3] + b1, 0.0f);
        int s = j >> 1;
        int fi = (j & 1) * 2;
        split2(v0, v1, Ah[s][fi],     Al[s][fi]);
        split2(v2, v3, Ah[s][fi + 1], Al[s][fi + 1]);
    }
}

// Gather layer-1 A fragments from the 8 live px float4 (even cols of x).
static __device__ __forceinline__ void frags_from_x(const float4 px[8],
                                                    uint32_t Ah[4][4], uint32_t Al[4][4]) {
#pragma unroll
    for (int s = 0; s < 2; s++) {
        const float4& f0 = px[s * 4 + 0];   // row r0,   col-half u=0
        const float4& f1 = px[s * 4 + 1];   // row r0,   col-half u=1
        const float4& f2 = px[s * 4 + 2];   // row r0+8, u=0
        const float4& f3 = px[s * 4 + 3];   // row r0+8, u=1
        split2(f0.x, f0.z, Ah[s][0], Al[s][0]);
        split2(f2.x, f2.z, Ah[s][1], Al[s][1]);
        split2(f1.x, f1.z, Ah[s][2], Al[s][2]);
        split2(f3.x, f3.z, Ah[s][3], Al[s][3]);
    }
}

static __device__ __forceinline__ void load_px(const float* xb, int r0, int t4, float4 px[8]) {
#pragma unroll
    for (int s = 0; s < 2; s++) {
        const float4* p0 = (const float4*)(xb + r0 * 64 + s * 32) + t4;
        const float4* p1 = (const float4*)(xb + (r0 + 8) * 64 + s * 32) + t4;
        px[s * 4 + 0] = __ldg(p0);
        px[s * 4 + 1] = __ldg(p0 + 4);
        px[s * 4 + 2] = __ldg(p1);
        px[s * 4 + 3] = __ldg(p1 + 4);
    }
}

__global__ void __launch_bounds__(TPB, 2)
affine_coupling_hmma(const float* __restrict__ x,
                     const float* __restrict__ W1, const float* __restrict__ b1,
                     const float* __restrict__ W2, const float* __restrict__ b2,
                     const float* __restrict__ W3, const float* __restrict__ b3,
                     float* __restrict__ out, int nrows) {
    extern __shared__ char sm[];
    const uint32_t smb = smem_u32_of(sm);

    const int tid  = threadIdx.x;
    const int wid  = tid >> 5;
    const int lane = tid & 31;
    const int g    = lane >> 2;
    const int t4   = lane & 3;
    const int lane15 = lane & 15;
    const uint32_t bufb = smb + ((lane & 16) ? WLO : WHI);
    const int r0 = wid * 16 + g;              // first owned row

    // ---- weight prep: bf16 hi/lo, SW128 swizzled [k][n] rows of 128B ----
    for (int e = tid; e < 10240; e += TPB) {
        const float* src; int rel, rb;
        if (e < 2048)      { src = W1; rel = e;        rb = 0;  }
        else if (e < 6144) { src = W2; rel = e - 2048; rb = 32; }
        else               { src = W3; rel = e - 6144; rb = 96; }
        int k = rel >> 6, n = rel & 63;
        float w = __ldg(src + rel);
        __nv_bfloat16 h = __float2bfloat16(w);
        float hf = __bfloat162float(h);
        __nv_bfloat16 l = __float2bfloat16(w - hf);
        uint32_t off = SWZ((uint32_t)((rb + k) * 128 + n * 2));
        *(__nv_bfloat16*)(sm + WHI + off) = h;
        *(__nv_bfloat16*)(sm + WLO + off) = l;
    }
    float* bias = (float*)(sm + BIAS_O);
    if (tid < 64) {
        bias[tid]       = __ldg(b1 + tid);
        bias[64 + tid]  = __ldg(b2 + tid);
        bias[128 + tid] = __ldg(b3 + tid);
    }
    __syncthreads();    // only barrier in the kernel

    const int ntiles = nrows / ROWS_PER_CTA;
    float* outs = out + (size_t)nrows * 64;   // s block base

    for (int tile = blockIdx.x; tile < ntiles; tile += gridDim.x) {
        const float* xb = x + (size_t)tile * ROWS_PER_CTA * 64;

        float4 px[8];
        load_px(xb, r0, t4, px);

        uint32_t Ah[4][4], Al[4][4];
        float C[8][4];

        frags_from_x(px, Ah, Al);

        // ---- 3 GEMM layers ----
        run_layer<2>(bufb, 0, lane15, Ah, Al, C);
        epi_relu_split(bias, t4, C, Ah, Al);
        run_layer<4>(bufb, 32, lane15, Ah, Al, C);
        epi_relu_split(bias + 64, t4, C, Ah, Al);
        run_layer<4>(bufb, 96, lane15, Ah, Al, C);

        // ---- register-direct epilogue: y AND s straight from px + C ----
        // px block (s,u): odd cols -> sigma = 16s+8u+2*t4 -> s in C[2s+u],
        // t in C[2s+u+4], same lane, rows r0 (frag 0,1) / r0+8 (frag 2,3).
        {
            const float* b3s = bias + 128;
            float4* oy = (float4*)out + (size_t)tile * (ROWS_PER_CTA * 16);
            float*  oss = outs + (size_t)tile * (ROWS_PER_CTA * 32);
#pragma unroll
            for (int s = 0; s < 2; s++) {
#pragma unroll
                for (int u = 0; u < 2; u++) {
                    int js = 2 * s + u, jt = js + 4;
                    int sig = 16 * s + 8 * u + 2 * t4;
                    float bs0 = b3s[sig], bs1 = b3s[sig + 1];
                    float bt0 = b3s[32 + sig], bt1 = b3s[32 + sig + 1];

                    float sa0 = tanh_fast(C[js][0] + bs0);
                    float sb0 = tanh_fast(C[js][1] + bs1);
                    float sa1 = tanh_fast(C[js][2] + bs0);
                    float sb1 = tanh_fast(C[js][3] + bs1);
                    float ta0 = C[jt][0] + bt0, tb0 = C[jt][1] + bt1;
                    float ta1 = C[jt][2] + bt0, tb1 = C[jt][3] + bt1;

                    // s straight to global (32B-aligned 32B chunks per warp)
                    *(float2*)(oss + (size_t)r0 * 32 + sig)       = make_float2(sa0, sb0);
                    *(float2*)(oss + (size_t)(r0 + 8) * 32 + sig) = make_float2(sa1, sb1);

                    // y straight from registers
                    float4 v0 = px[4 * s + u];          // row r0
                    float4 v1 = px[4 * s + 2 + u];      // row r0+8
                    v0.y = fmaf(v0.y, __expf(sa0), ta0);
                    v0.w = fmaf(v0.w, __expf(sb0), tb0);
                    v1.y = fmaf(v1.y, __expf(sa1), ta1);
                    v1.w = fmaf(v1.w, __expf(sb1), tb1);
                    int c4 = (32 * s + 16 * u) >> 2;    // float4 col index base
                    oy[r0 * 16 + c4 + t4]       = v0;
                    oy[(r0 + 8) * 16 + c4 + t4] = v1;
                }
            }
        }
        // no barrier: weights are read-only, all outputs register-sourced
    }
}

extern "C" void kernel_launch(void* const* d_in, const int* in_sizes, int n_in,
                              void* d_out, int out_size) {
    const float* x  = (const float*)d_in[0];
    const float* W1 = (const float*)d_in[1];
    const float* b1 = (const float*)d_in[2];
    const float* W2 = (const float*)d_in[3];
    const float* b2 = (const float*)d_in[4];
    const float* W3 = (const float*)d_in[5];
    const float* b3 = (const float*)d_in[6];
    float* out = (float*)d_out;

    const int nrows = in_sizes[0] / 64;
    const int ntiles = nrows / ROWS_PER_CTA;
    int grid = 296;                      // 2 CTAs/SM * 148 SMs
    if (grid > ntiles) grid = ntiles;

    static int smem_set = 0;
    if (!smem_set) {
        cudaFuncSetAttribute(affine_coupling_hmma,
                             cudaFuncAttributeMaxDynamicSharedMemorySize, SMEM_BYTES);
        smem_set = 1;
    }
    affine_coupling_hmma<<<grid, TPB, SMEM_BYTES>>>(x, W1, b1, W2, b2, W3, b3, out, nrows);
}

// round 10
// speedup vs baseline: 6.0082x; 1.5603x over previous
#include <cuda_runtime.h>
#include <cuda_fp16.h>
#include <cstdint>

// AffineCouplingLayer via legacy tensor pipe (mma.sync fp16, sm_100-safe).
// B=524288 rows, D=64. cin = even cols (32).
//   h1 = relu(cin@W1+b1); h2 = relu(h1@W2+b2); st = h2@W3+b3
//   s = tanh(st[:32]); y = x with odd cols = x_odd*exp(s)+t
// out = [ y (B*64 f32) | s (B*32 f32) ]
//
// SINGLE-PRODUCT FP16: fp16 rounding is 2^-12 -> predicted rel_err ~2-4e-4,
// safely under the 1e-3 threshold (bf16 single would fail; bf16 3-product
// measured 6.8e-6 with 3x the MMAs and 2x the LDSM traffic).
//
// Per-warp tile M=16, N=64; 8 warps/CTA -> 128 rows/CTA; 2 CTAs/SM.
// Activations register-resident across layers (C frag == next A frag).
// One ldmatrix.x4.trans feeds TWO j-chunks: lanes 0-15 address chunk j0,
// lanes 16-31 chunk j1 (same 16 weight rows).
// Register-direct epilogue (y AND s from regs), barrier-free tile loop.

#define TPB          256
#define ROWS_PER_CTA 128

// ---- SMEM layout (bytes) ----
#define WH      0            // 160 rows * 128B = 20480 (fp16 weights, SW128)
#define BIAS_O  20480        // 192 f32
#define SMEM_BYTES 21248

#define SWZ(o) ((o) ^ (((o) >> 3) & 0x70))

static __device__ __forceinline__ uint32_t smem_u32_of(const void* p) {
    uint32_t a;
    asm("{ .reg .u64 t; cvta.to.shared.u64 t, %1; cvt.u32.u64 %0, t; }" : "=r"(a) : "l"(p));
    return a;
}

// pack two f32 -> fp16x2 (lo in low half)
static __device__ __forceinline__ uint32_t pack_f16(float lo, float hi) {
    uint32_t r;
    asm("cvt.rn.f16x2.f32 %0, %1, %2;" : "=r"(r) : "f"(hi), "f"(lo));
    return r;
}

static __device__ __forceinline__ float tanh_fast(float v) {
    return 1.0f - __fdividef(2.0f, __expf(2.0f * v) + 1.0f);
}

static __device__ __forceinline__ void mma16816(float* c, const uint32_t* a,
                                                uint32_t b0, uint32_t b1) {
    asm volatile(
        "mma.sync.aligned.m16n8k16.row.col.f32.f16.f16.f32 "
        "{%0,%1,%2,%3}, {%4,%5,%6,%7}, {%8,%9}, {%0,%1,%2,%3};"
        : "+f"(c[0]), "+f"(c[1]), "+f"(c[2]), "+f"(c[3])
        : "r"(a[0]), "r"(a[1]), "r"(a[2]), "r"(a[3]), "r"(b0), "r"(b1));
}

static __device__ __forceinline__ void ldsm4t(uint32_t addr, uint32_t& b00, uint32_t& b01,
                                              uint32_t& b10, uint32_t& b11) {
    asm volatile("ldmatrix.sync.aligned.m8n8.x4.trans.shared.b16 {%0,%1,%2,%3}, [%4];"
                 : "=r"(b00), "=r"(b01), "=r"(b10), "=r"(b11) : "r"(addr));
}

// One GEMM layer: C[8][4] = A @ B, single fp16 product.
// One ldsm.x4 per j-pair: lanes 0-15 -> chunk j0, lanes 16-31 -> chunk j1.
template <int KS>
static __device__ __forceinline__ void run_layer(uint32_t wbase, int row_rb,
                                                 int lane15, int lanehi,
                                                 const uint32_t A[4][4], float C[8][4]) {
#pragma unroll
    for (int j = 0; j < 8; j++)
#pragma unroll
        for (int q = 0; q < 4; q++) C[j][q] = 0.0f;

#pragma unroll
    for (int s = 0; s < KS; s++) {
        int rowc = row_rb + s * 16 + lane15;
        uint32_t base = wbase + (uint32_t)rowc * 128;
        uint32_t x7 = (uint32_t)(rowc & 7);
#pragma unroll
        for (int jj = 0; jj < 4; jj++) {
            int j0 = 2 * jj, j1 = j0 + 1;
            uint32_t addr = base + ((uint32_t)((j0 + lanehi) ^ (int)x7) << 4);
            uint32_t b00, b01, b10, b11;
            ldsm4t(addr, b00, b01, b10, b11);
            mma16816(C[j0], A[s], b00, b01);
            mma16816(C[j1], A[s], b10, b11);
        }
    }
}

// bias + relu + fp16 pack: C (this layer) -> A fragments (next layer)
static __device__ __forceinline__ void epi_relu_pack(const float* bias, int t4,
                                                     const float C[8][4], uint32_t A[4][4]) {
#pragma unroll
    for (int j = 0; j < 8; j++) {
        float b0 = bias[8 * j + 2 * t4];
        float b1 = bias[8 * j + 2 * t4 + 1];
        float v0 = fmaxf(C[j][0] + b0, 0.0f);
        float v1 = fmaxf(C[j][1] + b1, 0.0f);
        float v2 = fmaxf(C[j][2] + b0, 0.0f);
        float v3 = fmaxf(C[j][3] + b1, 0.0f);
        int s = j >> 1;
        int fi = (j & 1) * 2;
        A[s][fi]     = pack_f16(v0, v1);
        A[s][fi + 1] = pack_f16(v2, v3);
    }
}

// Gather layer-1 A fragments from the 8 live px float4 (even cols of x).
static __device__ __forceinline__ void frags_from_x(const float4 px[8], uint32_t A[4][4]) {
#pragma unroll
    for (int s = 0; s < 2; s++) {
        const float4& f0 = px[s * 4 + 0];   // row r0,   col-half u=0
        const float4& f1 = px[s * 4 + 1];   // row r0,   col-half u=1
        const float4& f2 = px[s * 4 + 2];   // row r0+8, u=0
        const float4& f3 = px[s * 4 + 3];   // row r0+8, u=1
        A[s][0] = pack_f16(f0.x, f0.z);
        A[s][1] = pack_f16(f2.x, f2.z);
        A[s][2] = pack_f16(f1.x, f1.z);
        A[s][3] = pack_f16(f3.x, f3.z);
    }
}

static __device__ __forceinline__ void load_px(const float* xb, int r0, int t4, float4 px[8]) {
#pragma unroll
    for (int s = 0; s < 2; s++) {
        const float4* p0 = (const float4*)(xb + r0 * 64 + s * 32) + t4;
        const float4* p1 = (const float4*)(xb + (r0 + 8) * 64 + s * 32) + t4;
        px[s * 4 + 0] = __ldg(p0);
        px[s * 4 + 1] = __ldg(p0 + 4);
        px[s * 4 + 2] = __ldg(p1);
        px[s * 4 + 3] = __ldg(p1 + 4);
    }
}

__global__ void __launch_bounds__(TPB, 2)
affine_coupling_hmma(const float* __restrict__ x,
                     const float* __restrict__ W1, const float* __restrict__ b1,
                     const float* __restrict__ W2, const float* __restrict__ b2,
                     const float* __restrict__ W3, const float* __restrict__ b3,
                     float* __restrict__ out, int nrows) {
    extern __shared__ char sm[];
    const uint32_t smb = smem_u32_of(sm);

    const int tid  = threadIdx.x;
    const int wid  = tid >> 5;
    const int lane = tid & 31;
    const int g    = lane >> 2;
    const int t4   = lane & 3;
    const int lane15 = lane & 15;
    const int lanehi = (lane >> 4) & 1;       // 0: chunk j0, 1: chunk j1
    const int r0 = wid * 16 + g;              // first owned row

    // ---- weight prep: fp16, SW128 swizzled [k][n] rows of 128B ----
    for (int e = tid; e < 10240; e += TPB) {
        const float* src; int rel, rb;
        if (e < 2048)      { src = W1; rel = e;        rb = 0;  }
        else if (e < 6144) { src = W2; rel = e - 2048; rb = 32; }
        else               { src = W3; rel = e - 6144; rb = 96; }
        int k = rel >> 6, n = rel & 63;
        float w = __ldg(src + rel);
        uint32_t off = SWZ((uint32_t)((rb + k) * 128 + n * 2));
        *(__half*)(sm + WH + off) = __float2half_rn(w);
    }
    float* bias = (float*)(sm + BIAS_O);
    if (tid < 64) {
        bias[tid]       = __ldg(b1 + tid);
        bias[64 + tid]  = __ldg(b2 + tid);
        bias[128 + tid] = __ldg(b3 + tid);
    }
    __syncthreads();    // only barrier in the kernel

    const int ntiles = nrows / ROWS_PER_CTA;
    float* outs = out + (size_t)nrows * 64;   // s block base
    const uint32_t wbase = smb + WH;

    for (int tile = blockIdx.x; tile < ntiles; tile += gridDim.x) {
        const float* xb = x + (size_t)tile * ROWS_PER_CTA * 64;

        float4 px[8];
        load_px(xb, r0, t4, px);

        uint32_t A[4][4];
        float C[8][4];

        frags_from_x(px, A);

        // ---- 3 GEMM layers ----
        run_layer<2>(wbase, 0, lane15, lanehi, A, C);
        epi_relu_pack(bias, t4, C, A);
        run_layer<4>(wbase, 32, lane15, lanehi, A, C);
        epi_relu_pack(bias + 64, t4, C, A);
        run_layer<4>(wbase, 96, lane15, lanehi, A, C);

        // ---- register-direct epilogue: y AND s straight from px + C ----
        // px block (s,u): odd cols -> sigma = 16s+8u+2*t4 -> s in C[2s+u],
        // t in C[2s+u+4], same lane, rows r0 (frag 0,1) / r0+8 (frag 2,3).
        {
            const float* b3s = bias + 128;
            float4* oy = (float4*)out + (size_t)tile * (ROWS_PER_CTA * 16);
            float*  oss = outs + (size_t)tile * (ROWS_PER_CTA * 32);
#pragma unroll
            for (int s = 0; s < 2; s++) {
#pragma unroll
                for (int u = 0; u < 2; u++) {
                    int js = 2 * s + u, jt = js + 4;
                    int sig = 16 * s + 8 * u + 2 * t4;
                    float bs0 = b3s[sig], bs1 = b3s[sig + 1];
                    float bt0 = b3s[32 + sig], bt1 = b3s[32 + sig + 1];

                    float sa0 = tanh_fast(C[js][0] + bs0);
                    float sb0 = tanh_fast(C[js][1] + bs1);
                    float sa1 = tanh_fast(C[js][2] + bs0);
                    float sb1 = tanh_fast(C[js][3] + bs1);
                    float ta0 = C[jt][0] + bt0, tb0 = C[jt][1] + bt1;
                    float ta1 = C[jt][2] + bt0, tb1 = C[jt][3] + bt1;

                    // s straight to global (32B-aligned 32B chunks per warp)
                    *(float2*)(oss + (size_t)r0 * 32 + sig)       = make_float2(sa0, sb0);
                    *(float2*)(oss + (size_t)(r0 + 8) * 32 + sig) = make_float2(sa1, sb1);

                    // y straight from registers
                    float4 v0 = px[4 * s + u];          // row r0
                    float4 v1 = px[4 * s + 2 + u];      // row r0+8
                    v0.y = fmaf(v0.y, __expf(sa0), ta0);
                    v0.w = fmaf(v0.w, __expf(sb0), tb0);
                    v1.y = fmaf(v1.y, __expf(sa1), ta1);
                    v1.w = fmaf(v1.w, __expf(sb1), tb1);
                    int c4 = (32 * s + 16 * u) >> 2;    // float4 col index base
                    oy[r0 * 16 + c4 + t4]       = v0;
                    oy[(r0 + 8) * 16 + c4 + t4] = v1;
                }
            }
        }
        // no barrier: weights are read-only, all outputs register-sourced
    }
}

extern "C" void kernel_launch(void* const* d_in, const int* in_sizes, int n_in,
                              void* d_out, int out_size) {
    const float* x  = (const float*)d_in[0];
    const float* W1 = (const float*)d_in[1];
    const float* b1 = (const float*)d_in[2];
    const float* W2 = (const float*)d_in[3];
    const float* b2 = (const float*)d_in[4];
    const float* W3 = (const float*)d_in[5];
    const float* b3 = (const float*)d_in[6];
    float* out = (float*)d_out;

    const int nrows = in_sizes[0] / 64;
    const int ntiles = nrows / ROWS_PER_CTA;
    int grid = 296;                      // 2 CTAs/SM * 148 SMs
    if (grid > ntiles) grid = ntiles;

    static int smem_set = 0;
    if (!smem_set) {
        cudaFuncSetAttribute(affine_coupling_hmma,
                             cudaFuncAttributeMaxDynamicSharedMemorySize, SMEM_BYTES);
        smem_set = 1;
    }
    affine_coupling_hmma<<<grid, TPB, SMEM_BYTES>>>(x, W1, b1, W2, b2, W3, b3, out, nrows);
}